// round 17
// baseline (speedup 1.0000x reference)
#include <cuda_runtime.h>
#include <cuda_fp16.h>
#include <mma.h>
#include <math.h>
#include <stdint.h>
#include <cooperative_groups.h>

using namespace nvcuda;
namespace cg = cooperative_groups;

// Problem constants
#define BB   16
#define TD   64
#define TE   64
#define HD   512
#define G3   1536
#define VV   32000
#define LOGITS_ELEMS (BB*TD*VV)   // 32768000

// ---------------- scratch (__device__ globals, no allocation) ----------------
__device__ float g_xp   [BB*TD*G3];
__device__ float g_encp [BB*TE*HD];
__device__ float g_decp [BB*TD*HD];
__device__ float g_hlast[BB*HD];

// fp16 operands
__device__ __half g_Ah  [BB*TD*HD];
__device__ __half g_Bh  [(size_t)VV*HD];
__device__ __half g_ench[BB*TE*HD];
__device__ __half g_cat [BB*TD*2*HD];
__device__ __half g_Wae [HD*HD];
__device__ __half g_Wad [HD*HD];
__device__ __half g_Wdh [HD*2*HD];
__device__ __half g_xh  [BB*TD*HD];
__device__ __half g_Wih [G3*HD];

// ---------------- helpers ----------------
__device__ __forceinline__ uint32_t smem_u32(const void* p) {
    uint32_t a;
    asm("{ .reg .u64 t; cvta.to.shared.u64 t, %1; cvt.u32.u64 %0, t; }" : "=r"(a) : "l"(p));
    return a;
}
__device__ __forceinline__ void cp16(uint32_t s, const void* g) {
    asm volatile("cp.async.cg.shared.global [%0], [%1], 16;" :: "r"(s), "l"(g));
}
__device__ __forceinline__ void cvt8(const float* sp, __half* dp) {
    float4 v0 = *(const float4*)sp;
    float4 v1 = *(const float4*)(sp + 4);
    __half2* d = (__half2*)dp;
    d[0] = __floats2half2_rn(v0.x, v0.y);
    d[1] = __floats2half2_rn(v0.z, v0.w);
    d[2] = __floats2half2_rn(v1.x, v1.y);
    d[3] = __floats2half2_rn(v1.z, v1.w);
}
__device__ __forceinline__ float fast_sigmoid(float a) {
    return __fdividef(1.f, 1.f + __expf(-a));
}
__device__ __forceinline__ float fast_tanh_acc(float a) {
    float t = __expf(-2.f * a);
    return __fdividef(2.f, 1.f + t) - 1.f;
}
__device__ __forceinline__ float tanh_fast(float x) {
    float y;
    asm("tanh.approx.f32 %0, %1;" : "=f"(y) : "f"(x));
    return y;
}

// ---------------- merged convert A: x -> xh, W_ih -> Wih ----------------
#define NA1 (BB*TD*HD)
#define NA2 (G3*HD)
__global__ void convA(const float* __restrict__ x, const float* __restrict__ Wih)
{
    int i = (blockIdx.x * 256 + threadIdx.x) * 8;
    if (i < NA1) {
        cvt8(x + i, g_xh + i);
    } else {
        int j = i - NA1;
        if (j < NA2) cvt8(Wih + j, g_Wih + j);
    }
}

// ---------------- merged convert B ----------------
#define NB1 (HD*2*HD)
#define NB2 (HD*2*HD)
#define NB3 (BB*TE*HD)
__global__ void convB(const float* __restrict__ Wdense,
                      const float* __restrict__ Wattn,
                      const float* __restrict__ enc)
{
    int i = (blockIdx.x * 256 + threadIdx.x) * 8;
    if (i < NB1) {
        cvt8(Wdense + i, g_Wdh + i);
    } else if (i < NB1 + NB2) {
        int j = i - NB1;
        int row = j >> 10, col = j & 1023;
        __half* dst = (col < HD) ? (g_Wae + row * HD + col)
                                 : (g_Wad + row * HD + (col - HD));
        cvt8(Wattn + j, dst);
    } else {
        int j = i - NB1 - NB2;
        if (j < NB3) cvt8(enc + j, g_ench + j);
    }
}

__global__ void convWout(const float* __restrict__ W_out)
{
    int i = (blockIdx.x * 256 + threadIdx.x) * 8;
    cvt8(W_out + i, g_Bh + i);
}

// ---------------- cluster GRU scan: 16 clusters x 8 CTAs, 1 batch/cluster ----------------
// CTA rank r holds fp16 W_hh rows [r*192,(r+1)*192) in SMEM.
// Step: phase1 matvec (192 thr, 4 accumulators; thr 192-255 prefetch x_proj) | sync |
//       phase2 gates for j in [r*64,(r+1)*64), DSMEM pre reads (hoisted ptrs),
//       h broadcast via 8 remote stores | sync.
#define RPC   192
#define WPAD  65
#define SMEM_W    (RPC * WPAD * 16)        // 199680
#define OFF_SH    SMEM_W                   // float sh[512]   (2048)
#define OFF_SPRE  (OFF_SH + 2048)          // float spre[192] (768)
#define OFF_SPX   (OFF_SPRE + 768)         // float spx[1536] (6144)
#define SMEM_GRU  (OFF_SPX + 6144)         // 206592

__global__ void __cluster_dims__(8, 1, 1) __launch_bounds__(256, 1)
gru_scan(const float* __restrict__ W_hh,
         const float* __restrict__ b_hh,
         const int*   __restrict__ lengths)
{
    extern __shared__ __align__(16) char dsm[];
    uint4* sWv  = (uint4*)dsm;
    float* sh   = (float*)(dsm + OFF_SH);
    float* spre = (float*)(dsm + OFF_SPRE);
    float* spx  = (float*)(dsm + OFF_SPX);

    cg::cluster_group cluster = cg::this_cluster();
    const int rank = (int)cluster.block_rank();     // 0..7
    const int bb   = blockIdx.x >> 3;               // batch 0..15
    const int tid  = threadIdx.x;

    // load my W_hh slice as fp16
    const int grow0 = rank * RPC;
    for (int idx = tid; idx < RPC * 64; idx += 256) {
        int row = idx >> 6, g = idx & 63;
        const float* src = W_hh + (size_t)(grow0 + row) * HD + g * 8;
        float4 a = *(const float4*)src;
        float4 b = *(const float4*)(src + 4);
        __half2 p0 = __floats2half2_rn(a.x, a.y);
        __half2 p1 = __floats2half2_rn(a.z, a.w);
        __half2 p2 = __floats2half2_rn(b.x, b.y);
        __half2 p3 = __floats2half2_rn(b.z, b.w);
        uint4 v;
        v.x = *reinterpret_cast<uint32_t*>(&p0);
        v.y = *reinterpret_cast<uint32_t*>(&p1);
        v.z = *reinterpret_cast<uint32_t*>(&p2);
        v.w = *reinterpret_cast<uint32_t*>(&p3);
        sWv[row * WPAD + g] = v;
    }
    for (int i = tid; i < 512; i += 256) sh[i] = 0.f;
    const int len = lengths[bb];
    __syncthreads();

    // phase-2 constants (tid < 64)
    const int j  = rank * 64 + (tid & 63);
    const int gr = j, gz = 512 + j, gn = 1024 + j;
    const float* rpr = (const float*)cluster.map_shared_rank(spre, gr / RPC) + (gr % RPC);
    const float* rpz = (const float*)cluster.map_shared_rank(spre, gz / RPC) + (gz % RPC);
    const float* rpn = (const float*)cluster.map_shared_rank(spre, gn / RPC) + (gn % RPC);
    float* hb0 = (float*)cluster.map_shared_rank(sh, 0) + j;
    float* hb1 = (float*)cluster.map_shared_rank(sh, 1) + j;
    float* hb2 = (float*)cluster.map_shared_rank(sh, 2) + j;
    float* hb3 = (float*)cluster.map_shared_rank(sh, 3) + j;
    float* hb4 = (float*)cluster.map_shared_rank(sh, 4) + j;
    float* hb5 = (float*)cluster.map_shared_rank(sh, 5) + j;
    float* hb6 = (float*)cluster.map_shared_rank(sh, 6) + j;
    float* hb7 = (float*)cluster.map_shared_rank(sh, 7) + j;
    float bhr = 0.f, bhz = 0.f, bhn = 0.f;
    if (tid < 64) { bhr = b_hh[gr]; bhz = b_hh[gz]; bhn = b_hh[gn]; }

    cluster.sync();   // W/sh init visible cluster-wide before first DSMEM access

    for (int t = 0; t < TD; t++) {
        // ---- phase 1 ----
        if (tid < RPC) {
            const uint4* wrow = sWv + tid * WPAD;
            float a0 = 0.f, a1 = 0.f, a2 = 0.f, a3 = 0.f;
            #pragma unroll 4
            for (int g = 0; g < 64; g++) {
                uint4 w = wrow[g];
                __half2 w0 = *reinterpret_cast<__half2*>(&w.x);
                __half2 w1 = *reinterpret_cast<__half2*>(&w.y);
                __half2 w2 = *reinterpret_cast<__half2*>(&w.z);
                __half2 w3 = *reinterpret_cast<__half2*>(&w.w);
                float2 f0 = __half22float2(w0), f1 = __half22float2(w1);
                float2 f2 = __half22float2(w2), f3 = __half22float2(w3);
                float4 hA = *(const float4*)(sh + g * 8);
                float4 hB = *(const float4*)(sh + g * 8 + 4);
                a0 += f0.x * hA.x + f0.y * hA.y;
                a1 += f1.x * hA.z + f1.y * hA.w;
                a2 += f2.x * hB.x + f2.y * hB.y;
                a3 += f3.x * hB.z + f3.y * hB.w;
            }
            spre[tid] = (a0 + a1) + (a2 + a3);
        } else {
            // threads 192-255 prefetch this step's x_proj row
            int i2 = tid - RPC;   // 0..63
            const float4* x0 = (const float4*)(g_xp + ((size_t)bb * TD + t) * G3);
            float4* d0 = (float4*)spx;
            #pragma unroll
            for (int q = 0; q < 6; q++)
                d0[i2 + q * 64] = x0[i2 + q * 64];
        }
        cluster.sync();

        // ---- phase 2: gates for my 64-j slice ----
        if (tid < 64) {
            float pr = *rpr + bhr;
            float pz = *rpz + bhz;
            float pn = *rpn + bhn;
            float r = fast_sigmoid(spx[j] + pr);
            float z = fast_sigmoid(spx[512 + j] + pz);
            float n = fast_tanh_acc(spx[1024 + j] + r * pn);
            float hold = sh[j];
            float hnew = (1.f - z) * n + z * hold;
            bool valid = (t < len);
            float hkeep = valid ? hnew : hold;
            *hb0 = hkeep; *hb1 = hkeep; *hb2 = hkeep; *hb3 = hkeep;
            *hb4 = hkeep; *hb5 = hkeep; *hb6 = hkeep; *hb7 = hkeep;
            g_cat[((size_t)bb * TD + t) * (2 * HD) + j] = __float2half(valid ? hnew : 0.f);
            if (t == TD - 1) g_hlast[(size_t)bb * HD + j] = hkeep;
        }
        cluster.sync();
    }
}

// ---------------- attention (unchanged) ----------------
__global__ void attn_kernel(const float* __restrict__ encp,
                            const float* __restrict__ decp,
                            const float* __restrict__ enc,
                            const int*   __restrict__ dlen,
                            const int*   __restrict__ elen,
                            const float* __restrict__ b_attn,
                            const float* __restrict__ v_w,
                            __half* __restrict__ cat)
{
    const int bd = blockIdx.x;
    const int b  = bd >> 6;
    const int d  = bd & 63;
    const int tid = threadIdx.x;

    __shared__ float s_dp[HD];
    __shared__ float s_vw[HD];
    __shared__ float s_en[TE];
    __shared__ float s_mx, s_ssum;

    __half* ctx_out = cat + (size_t)bd * (2 * HD) + HD;
    const int Dl = dlen[b];
    const int El = elen[b];

    if (d >= Dl) {
        for (int i = tid; i < HD; i += 256) ctx_out[i] = __float2half(0.f);
        return;
    }

    for (int i = tid; i < HD; i += 256) {
        s_dp[i] = decp[(size_t)bd * HD + i] + b_attn[i];
        s_vw[i] = v_w[i];
    }
    __syncthreads();

    const int warp = tid >> 5, lane = tid & 31;
    for (int e = warp; e < El; e += 8) {
        const float* ep = encp + ((size_t)b * TE + e) * HD;
        float sum = 0.f;
        #pragma unroll 4
        for (int h = lane; h < HD; h += 32)
            sum += tanh_fast(ep[h] + s_dp[h]) * s_vw[h];
        #pragma unroll
        for (int off = 16; off; off >>= 1)
            sum += __shfl_xor_sync(0xffffffffu, sum, off);
        if (lane == 0) s_en[e] = sum;
    }
    __syncthreads();

    if (tid < 32) {
        float mx = -1e30f;
        for (int e = lane; e < El; e += 32) mx = fmaxf(mx, s_en[e]);
        #pragma unroll
        for (int off = 16; off; off >>= 1)
            mx = fmaxf(mx, __shfl_xor_sync(0xffffffffu, mx, off));
        float ss = 0.f;
        for (int e = lane; e < El; e += 32) ss += __expf(s_en[e] - mx);
        #pragma unroll
        for (int off = 16; off; off >>= 1)
            ss += __shfl_xor_sync(0xffffffffu, ss, off);
        if (lane == 0) { s_mx = mx; s_ssum = ss; }
    }
    __syncthreads();
    if (tid < TE) s_en[tid] = (tid < El) ? __fdividef(__expf(s_en[tid] - s_mx), s_ssum) : 0.f;
    __syncthreads();

    for (int h = tid; h < HD; h += 256) {
        float a = 0.f;
        for (int e = 0; e < El; e++)
            a += s_en[e] * enc[((size_t)b * TE + e) * HD + h];
        ctx_out[h] = __float2half(a);
    }
}

// ---------------- generic fp16 wmma NT GEMM (unchanged) ----------------
#define HF_TANH 1
#define HF_OUTH 2
#define HLDT 72
#define HARR (64 * HLDT)
#define HSTAGE (2 * HARR)
#define HSMEM (2 * HSTAGE * 2)
#define HLDC 36

__device__ __forceinline__ void hload_stage(const __half* __restrict__ A, int lda,
                                            const __half* __restrict__ B, int ldb,
                                            int row0, int n0, int c,
                                            uint32_t smbase, int s, int tid)
{
    #pragma unroll
    for (int it = 0; it < 4; it++) {
        int i = tid + it * 128;
        int r = i >> 3, c4 = i & 7;
        const void* src = A + (size_t)(row0 + r) * lda + c * 64 + c4 * 8;
        cp16(smbase + (uint32_t)(s * HSTAGE) * 2u + (uint32_t)(r * (HLDT * 2) + c4 * 16), src);
    }
    #pragma unroll
    for (int it = 0; it < 4; it++) {
        int i = tid + it * 128;
        int r = i >> 3, c4 = i & 7;
        const void* src = B + (size_t)(n0 + r) * ldb + c * 64 + c4 * 8;
        cp16(smbase + (uint32_t)(s * HSTAGE + HARR) * 2u + (uint32_t)(r * (HLDT * 2) + c4 * 16), src);
    }
    asm volatile("cp.async.commit_group;" ::: "memory");
}

__global__ void __launch_bounds__(128, 2) hgemm_nt(
    const __half* __restrict__ A, int lda,
    const __half* __restrict__ B, int ldb,
    const float* __restrict__ bias,
    void* __restrict__ Cout, int ldc,
    int K, int flags)
{
    extern __shared__ __align__(16) char dsm[];
    __half* sm = (__half*)dsm;
    const uint32_t smbase = smem_u32(dsm);

    const int tid = threadIdx.x;
    const int wid = tid >> 5, lane = tid & 31;
    const int brow0 = blockIdx.y * 64;
    const int bn0   = blockIdx.x * 64;
    const int warp_m = wid >> 1, warp_n = wid & 1;
    const int nch = K / 64;

    wmma::fragment<wmma::accumulator, 16, 16, 16, float> acc[2][2];
    #pragma unroll
    for (int i = 0; i < 2; i++)
        #pragma unroll
        for (int j = 0; j < 2; j++)
            wmma::fill_fragment(acc[i][j], 0.f);

    hload_stage(A, lda, B, ldb, brow0, bn0, 0, smbase, 0, tid);
    hload_stage(A, lda, B, ldb, brow0, bn0, 1, smbase, 1, tid);

    for (int c = 0; c < nch; c++) {
        const int s = c & 1;
        if (c < nch - 1) asm volatile("cp.async.wait_group 1;" ::: "memory");
        else             asm volatile("cp.async.wait_group 0;" ::: "memory");
        __syncthreads();

        const __half* As = sm + s * HSTAGE;
        const __half* Bs = As + HARR;

        #pragma unroll
        for (int kk = 0; kk < 64; kk += 16) {
            wmma::fragment<wmma::matrix_a, 16, 16, 16, __half, wmma::row_major> a[2];
            wmma::fragment<wmma::matrix_b, 16, 16, 16, __half, wmma::col_major> b[2];
            #pragma unroll
            for (int i = 0; i < 2; i++)
                wmma::load_matrix_sync(a[i], As + (warp_m * 32 + i * 16) * HLDT + kk, HLDT);
            #pragma unroll
            for (int j = 0; j < 2; j++)
                wmma::load_matrix_sync(b[j], Bs + (warp_n * 32 + j * 16) * HLDT + kk, HLDT);
            #pragma unroll
            for (int i = 0; i < 2; i++)
                #pragma unroll
                for (int j = 0; j < 2; j++)
                    wmma::mma_sync(acc[i][j], a[i], b[j], acc[i][j]);
        }
        __syncthreads();

        if (c + 2 < nch) hload_stage(A, lda, B, ldb, brow0, bn0, c + 2, smbase, s, tid);
    }

    __syncthreads();
    float* ws = (float*)dsm + wid * 32 * HLDC;
    #pragma unroll
    for (int i = 0; i < 2; i++)
        #pragma unroll
        for (int j = 0; j < 2; j++)
            wmma::store_matrix_sync(ws + i * 16 * HLDC + j * 16, acc[i][j],
                                    HLDC, wmma::mem_row_major);
    __syncwarp();

    const int row0 = brow0 + warp_m * 32;
    const int n0   = bn0 + warp_n * 32;
    #pragma unroll
    for (int it = 0; it < 8; it++) {
        int idx = lane + it * 32;
        int r   = idx >> 3;
        int c4  = (idx & 7) * 4;
        float4 v = *(float4*)(ws + r * HLDC + c4);
        if (bias) {
            v.x += bias[n0 + c4 + 0];
            v.y += bias[n0 + c4 + 1];
            v.z += bias[n0 + c4 + 2];
            v.w += bias[n0 + c4 + 3];
        }
        if (flags & HF_TANH) {
            v.x = fast_tanh_acc(v.x); v.y = fast_tanh_acc(v.y);
            v.z = fast_tanh_acc(v.z); v.w = fast_tanh_acc(v.w);
        }
        if (flags & HF_OUTH) {
            __half* cp = (__half*)Cout + (size_t)(row0 + r) * ldc + n0 + c4;
            *(__half2*)(cp)     = __floats2half2_rn(v.x, v.y);
            *(__half2*)(cp + 2) = __floats2half2_rn(v.z, v.w);
        } else {
            *(float4*)((float*)Cout + (size_t)(row0 + r) * ldc + n0 + c4) = v;
        }
    }
}

// ---------------- wmma logits GEMM (unchanged) ----------------
#define LBK   64
#define LDT   72
#define ARR_ELEMS (128 * LDT)
#define STAGE_ELEMS (2 * ARR_ELEMS)
#define LDC_W 68
#define SMEM_LOGITS 73728

__device__ __forceinline__ void load_stage_logits(int tid, int mt, int nt, int c,
                                                  uint32_t smbase, int s)
{
    const __half* srcs[2] = {
        g_Ah + (size_t)mt * 128 * HD,
        g_Bh + (size_t)nt * 128 * HD
    };
    #pragma unroll
    for (int arr = 0; arr < 2; arr++) {
        #pragma unroll
        for (int it = 0; it < 8; it++) {
            int i  = tid + it * 128;
            int r  = i >> 3;
            int g  = i & 7;
            const void* src = srcs[arr] + (size_t)r * HD + c * LBK + g * 8;
            uint32_t dst = smbase + (uint32_t)(s * STAGE_ELEMS + arr * ARR_ELEMS) * 2u
                         + (uint32_t)(r * (LDT * 2) + g * 16);
            cp16(dst, src);
        }
    }
    asm volatile("cp.async.commit_group;" ::: "memory");
}

__global__ void __launch_bounds__(128, 2) logits_wmma(const float* __restrict__ b_out,
                                                      float* __restrict__ out)
{
    extern __shared__ __align__(16) char dynsmem[];
    __half* sm = (__half*)dynsmem;
    const uint32_t smbase = smem_u32(dynsmem);

    const int tid = threadIdx.x;
    const int wid = tid >> 5, lane = tid & 31;
    const int nt = blockIdx.x;
    const int mt = blockIdx.y;
    const int warp_m = wid >> 1;
    const int warp_n = wid & 1;

    wmma::fragment<wmma::accumulator, 16, 16, 16, float> acc[4][4];
    #pragma unroll
    for (int i = 0; i < 4; i++)
        #pragma unroll
        for (int j = 0; j < 4; j++)
            wmma::fill_fragment(acc[i][j], 0.f);

    load_stage_logits(tid, mt, nt, 0, smbase, 0);
    load_stage_logits(tid, mt, nt, 1, smbase, 1);

    for (int c = 0; c < 8; c++) {
        const int s = c & 1;
        if (c < 7) asm volatile("cp.async.wait_group 1;" ::: "memory");
        else       asm volatile("cp.async.wait_group 0;" ::: "memory");
        __syncthreads();

        const __half* As = sm + s * STAGE_ELEMS;
        const __half* Bs = As + ARR_ELEMS;

        #pragma unroll
        for (int kk = 0; kk < LBK; kk += 16) {
            wmma::fragment<wmma::matrix_a, 16, 16, 16, __half, wmma::row_major> a[4];
            wmma::fragment<wmma::matrix_b, 16, 16, 16, __half, wmma::col_major> b[4];
            #pragma unroll
            for (int i = 0; i < 4; i++)
                wmma::load_matrix_sync(a[i], As + (warp_m * 64 + i * 16) * LDT + kk, LDT);
            #pragma unroll
            for (int j = 0; j < 4; j++)
                wmma::load_matrix_sync(b[j], Bs + (warp_n * 64 + j * 16) * LDT + kk, LDT);
            #pragma unroll
            for (int i = 0; i < 4; i++)
                #pragma unroll
                for (int j = 0; j < 4; j++)
                    wmma::mma_sync(acc[i][j], a[i], b[j], acc[i][j]);
        }
        __syncthreads();

        if (c + 2 < 8) load_stage_logits(tid, mt, nt, c + 2, smbase, s);
    }

    __syncthreads();
    float* ws = (float*)dynsmem + wid * 64 * LDC_W;
    #pragma unroll
    for (int i = 0; i < 4; i++)
        #pragma unroll
        for (int j = 0; j < 4; j++)
            wmma::store_matrix_sync(ws + i * 16 * LDC_W + j * 16, acc[i][j],
                                    LDC_W, wmma::mem_row_major);
    __syncwarp();

    const int row0 = mt * 128 + warp_m * 64;
    const int n0   = nt * 128 + warp_n * 64;
    #pragma unroll
    for (int it = 0; it < 32; it++) {
        int idx = lane + it * 32;
        int r   = idx >> 4;
        int c4  = (idx & 15) * 4;
        float4 v = *(float4*)(ws + r * LDC_W + c4);
        v.x += b_out[n0 + c4 + 0];
        v.y += b_out[n0 + c4 + 1];
        v.z += b_out[n0 + c4 + 2];
        v.w += b_out[n0 + c4 + 3];
        *(float4*)(out + (size_t)(row0 + r) * VV + n0 + c4) = v;
    }
}

// ---------------- launch ----------------
extern "C" void kernel_launch(void* const* d_in, const int* in_sizes, int n_in,
                              void* d_out, int out_size)
{
    const float* x      = (const float*)d_in[0];
    const int*   inlen  = (const int*)  d_in[1];
    const float* enc    = (const float*)d_in[2];
    const int*   enclen = (const int*)  d_in[3];
    const float* W_ih   = (const float*)d_in[4];
    const float* W_hh   = (const float*)d_in[5];
    const float* b_ih   = (const float*)d_in[6];
    const float* b_hh   = (const float*)d_in[7];
    const float* W_attn = (const float*)d_in[8];
    const float* b_attn = (const float*)d_in[9];
    const float* v_w    = (const float*)d_in[10];
    const float* W_dense= (const float*)d_in[12];
    const float* b_dense= (const float*)d_in[13];
    const float* W_out  = (const float*)d_in[14];
    const float* b_out  = (const float*)d_in[15];

    float* out = (float*)d_out;

    float* xp    = nullptr; cudaGetSymbolAddress((void**)&xp,    g_xp);
    float* encp  = nullptr; cudaGetSymbolAddress((void**)&encp,  g_encp);
    float* decp  = nullptr; cudaGetSymbolAddress((void**)&decp,  g_decp);
    float* hlast = nullptr; cudaGetSymbolAddress((void**)&hlast, g_hlast);
    __half* Ah   = nullptr; cudaGetSymbolAddress((void**)&Ah,   g_Ah);
    __half* ench = nullptr; cudaGetSymbolAddress((void**)&ench, g_ench);
    __half* cat  = nullptr; cudaGetSymbolAddress((void**)&cat,  g_cat);
    __half* Wae  = nullptr; cudaGetSymbolAddress((void**)&Wae,  g_Wae);
    __half* Wad  = nullptr; cudaGetSymbolAddress((void**)&Wad,  g_Wad);
    __half* Wdh  = nullptr; cudaGetSymbolAddress((void**)&Wdh,  g_Wdh);
    __half* xh   = nullptr; cudaGetSymbolAddress((void**)&xh,   g_xh);
    __half* Wih  = nullptr; cudaGetSymbolAddress((void**)&Wih,  g_Wih);

    cudaFuncSetAttribute(logits_wmma, cudaFuncAttributeMaxDynamicSharedMemorySize, SMEM_LOGITS);
    cudaFuncSetAttribute(gru_scan,    cudaFuncAttributeMaxDynamicSharedMemorySize, SMEM_GRU);

    // #1: merged convert (x, W_ih)
    convA<<<(NA1 + NA2) / 2048, 256>>>(x, W_ih);

    // #2: x_proj
    hgemm_nt<<<dim3(G3 / 64, (BB * TD) / 64), 128, HSMEM>>>(xh, HD, Wih, HD, b_ih, xp, G3, HD, 0);

    // #3: W_out convert
    convWout<<<((size_t)VV * HD) / 2048, 256>>>(W_out);

    // #4: cluster GRU scan (16 clusters x 8 CTAs, 1 batch each)
    gru_scan<<<128, 256, SMEM_GRU>>>(W_hh, b_hh, inlen);

    // #5: merged convert (W_dense, W_attn, enc)
    convB<<<(NB1 + NB2 + NB3) / 2048, 256>>>(W_dense, W_attn, enc);

    // #6,7: attention projections
    hgemm_nt<<<dim3(HD / 64, (BB * TE) / 64), 128, HSMEM>>>(ench, HD, Wae, HD, nullptr, encp, HD, HD, 0);
    hgemm_nt<<<dim3(HD / 64, (BB * TD) / 64), 128, HSMEM>>>(cat, 2 * HD, Wad, HD, nullptr, decp, HD, HD, 0);

    // #8: attention
    attn_kernel<<<BB * TD, 256>>>(encp, decp, enc, inlen, enclen, b_attn, v_w, cat);

    // #9: dense
    hgemm_nt<<<dim3(HD / 64, (BB * TD) / 64), 128, HSMEM>>>(cat, 2 * HD, Wdh, 2 * HD, b_dense, Ah, HD,
                                                            2 * HD, HF_TANH | HF_OUTH);

    // #10: logits
    logits_wmma<<<dim3(VV / 128, (BB * TD) / 128), 128, SMEM_LOGITS>>>(b_out, out);

    // h_last tail via async D2D copy
    cudaMemcpyAsync(out + LOGITS_ELEMS, hlast, BB * HD * sizeof(float),
                    cudaMemcpyDeviceToDevice);
}